// round 1
// baseline (speedup 1.0000x reference)
#include <cuda_runtime.h>
#include <cstdint>

// Problem shape (fixed for this dataset entry)
#define B 8
#define H 12
#define S 4096
#define D 64
#define BH (B*H)        // 96
#define TOPK 128

// Scratch (device globals; no allocation allowed)
__device__ float g_imp[BH * S];     // importance scores
__device__ int   g_idx[BH * TOPK];  // selected indices per head

// ---------------------------------------------------------------------------
// Kernel 1: importance = mean + std(ddof=1) over last dim (D=64).
// One warp per row; two-pass (mean, then sum of squared deviations) to match
// jnp.std semantics as closely as possible.
// ---------------------------------------------------------------------------
__global__ void imp_kernel(const float* __restrict__ q) {
    int warp = (blockIdx.x * blockDim.x + threadIdx.x) >> 5;
    int lane = threadIdx.x & 31;
    if (warp >= BH * S) return;
    const float2 v = reinterpret_cast<const float2*>(q + (size_t)warp * D)[lane];
    float s = v.x + v.y;
    #pragma unroll
    for (int o = 16; o; o >>= 1) s += __shfl_xor_sync(0xFFFFFFFFu, s, o);
    float mean = s * (1.0f / 64.0f);
    float dx = v.x - mean, dy = v.y - mean;
    float s2 = dx * dx + dy * dy;
    #pragma unroll
    for (int o = 16; o; o >>= 1) s2 += __shfl_xor_sync(0xFFFFFFFFu, s2, o);
    if (lane == 0) g_imp[warp] = mean + sqrtf(s2 * (1.0f / 63.0f));
}

// ---------------------------------------------------------------------------
// Kernel 2: exact top-128 selection per (b,h) via binary search on
// order-preserving uint keys. One block per head.
// ---------------------------------------------------------------------------
__global__ void topk_kernel() {
    __shared__ unsigned keys[S];   // 16 KB
    __shared__ int s_cnt;
    __shared__ int s_n;
    int bh = blockIdx.x;
    const float* row = g_imp + (size_t)bh * S;

    for (int i = threadIdx.x; i < S; i += blockDim.x) {
        unsigned u = __float_as_uint(row[i]);
        // monotone map: larger float -> larger uint
        u = (u & 0x80000000u) ? ~u : (u | 0x80000000u);
        keys[i] = u;
    }
    __syncthreads();

    // Binary search for T = 128th-largest key: max T s.t. count(>=T) >= TOPK
    unsigned lo = 0u, hi = 0xFFFFFFFFu;
    while (lo < hi) {
        unsigned mid = lo + ((hi - lo) >> 1) + 1u;
        if (threadIdx.x == 0) s_cnt = 0;
        __syncthreads();
        int c = 0;
        for (int i = threadIdx.x; i < S; i += blockDim.x) c += (keys[i] >= mid);
        #pragma unroll
        for (int o = 16; o; o >>= 1) c += __shfl_xor_sync(0xFFFFFFFFu, c, o);
        if ((threadIdx.x & 31) == 0) atomicAdd(&s_cnt, c);
        __syncthreads();
        int cnt = s_cnt;
        if (cnt >= TOPK) lo = mid; else hi = mid - 1u;
        __syncthreads();   // protect s_cnt reuse next iteration
    }
    unsigned T = lo;

    if (threadIdx.x == 0) s_n = 0;
    __syncthreads();
    // strictly-greater first
    for (int i = threadIdx.x; i < S; i += blockDim.x) {
        if (keys[i] > T) {
            int p = atomicAdd(&s_n, 1);
            g_idx[bh * TOPK + p] = i;
        }
    }
    __syncthreads();
    // fill remaining slots with == T (count(>=T) == TOPK almost surely, so
    // all equals are included and order does not matter)
    for (int i = threadIdx.x; i < S; i += blockDim.x) {
        if (keys[i] == T) {
            int p = atomicAdd(&s_n, 1);
            if (p < TOPK) g_idx[bh * TOPK + p] = i;
        }
    }
}

// ---------------------------------------------------------------------------
// Kernel 3: gathered attention per head.
//   scores = q_s k_s^T / 8 -> softmax -> @ v_s; scatter rows to output.
// 256 threads, register-tiled fp32 GEMMs in shared memory.
// ---------------------------------------------------------------------------
#define PITCH 68   // floats per smem row (128B data + pad: conflict-free LDS.128)

__global__ __launch_bounds__(256, 1)
void attn_kernel(const float* __restrict__ q, const float* __restrict__ k,
                 const float* __restrict__ v, float* __restrict__ out) {
    extern __shared__ float sm[];
    float* qs = sm;                        // 128 x PITCH
    float* ks = qs + TOPK * PITCH;
    float* vs = ks + TOPK * PITCH;
    float* sc = vs + TOPK * PITCH;         // 128 x 128 scores
    __shared__ int sidx[TOPK];

    const int bh  = blockIdx.x;
    const int tid = threadIdx.x;
    if (tid < TOPK) sidx[tid] = g_idx[bh * TOPK + tid];
    __syncthreads();

    const size_t base = (size_t)bh * S * D;

    // Gather q_s,k_s,v_s: 2 threads per row, 8 float4 each
    {
        int r = tid >> 1, half = tid & 1;
        size_t goff = base + (size_t)sidx[r] * D + half * 32;
        const float4* gq = reinterpret_cast<const float4*>(q + goff);
        const float4* gk = reinterpret_cast<const float4*>(k + goff);
        const float4* gv = reinterpret_cast<const float4*>(v + goff);
        float* dq = qs + r * PITCH + half * 32;
        float* dk = ks + r * PITCH + half * 32;
        float* dv = vs + r * PITCH + half * 32;
        #pragma unroll
        for (int i = 0; i < 8; i++) {
            reinterpret_cast<float4*>(dq)[i] = gq[i];
            reinterpret_cast<float4*>(dk)[i] = gk[i];
            reinterpret_cast<float4*>(dv)[i] = gv[i];
        }
    }
    __syncthreads();

    const int tx = tid & 15, ty = tid >> 4;

    // GEMM1: scores[r][c] = dot(q_s[r], k_s[c]); 8x8 tile per thread, strided
    {
        float acc[8][8];
        #pragma unroll
        for (int i = 0; i < 8; i++)
            #pragma unroll
            for (int j = 0; j < 8; j++) acc[i][j] = 0.0f;

        #pragma unroll
        for (int d = 0; d < D; d += 4) {
            float4 a[8], b[8];
            #pragma unroll
            for (int i = 0; i < 8; i++)
                a[i] = *reinterpret_cast<const float4*>(qs + (ty + 16 * i) * PITCH + d);
            #pragma unroll
            for (int j = 0; j < 8; j++)
                b[j] = *reinterpret_cast<const float4*>(ks + (tx + 16 * j) * PITCH + d);
            #pragma unroll
            for (int i = 0; i < 8; i++)
                #pragma unroll
                for (int j = 0; j < 8; j++) {
                    acc[i][j] += a[i].x * b[j].x;
                    acc[i][j] += a[i].y * b[j].y;
                    acc[i][j] += a[i].z * b[j].z;
                    acc[i][j] += a[i].w * b[j].w;
                }
        }
        const float scale = 0.125f;  // 1/sqrt(64)
        #pragma unroll
        for (int i = 0; i < 8; i++)
            #pragma unroll
            for (int j = 0; j < 8; j++)
                sc[(ty + 16 * i) * TOPK + (tx + 16 * j)] = acc[i][j] * scale;
    }
    __syncthreads();

    // Softmax over rows (one warp per 16 rows)
    {
        int lane = tid & 31, wid = tid >> 5;
        for (int r = wid; r < TOPK; r += 8) {
            float* row = sc + r * TOPK;
            float x[4];
            float m = -1e30f;
            #pragma unroll
            for (int c = 0; c < 4; c++) { x[c] = row[lane + 32 * c]; m = fmaxf(m, x[c]); }
            #pragma unroll
            for (int o = 16; o; o >>= 1) m = fmaxf(m, __shfl_xor_sync(0xFFFFFFFFu, m, o));
            float ssum = 0.0f;
            #pragma unroll
            for (int c = 0; c < 4; c++) { x[c] = __expf(x[c] - m); ssum += x[c]; }
            #pragma unroll
            for (int o = 16; o; o >>= 1) ssum += __shfl_xor_sync(0xFFFFFFFFu, ssum, o);
            float inv = 1.0f / ssum;
            #pragma unroll
            for (int c = 0; c < 4; c++) row[lane + 32 * c] = x[c] * inv;
        }
    }
    __syncthreads();

    // GEMM2: out_s[r][d] = sum_s attn[r][s] * v_s[s][d]; 8x4 tile per thread
    {
        float acc2[8][4];
        #pragma unroll
        for (int i = 0; i < 8; i++)
            #pragma unroll
            for (int j = 0; j < 4; j++) acc2[i][j] = 0.0f;

        #pragma unroll 4
        for (int s0 = 0; s0 < TOPK; s0 += 4) {
            float4 a4[8];
            #pragma unroll
            for (int i = 0; i < 8; i++)
                a4[i] = *reinterpret_cast<const float4*>(sc + (ty + 16 * i) * TOPK + s0);
            float b0[4], b1[4], b2[4], b3[4];
            #pragma unroll
            for (int j = 0; j < 4; j++) {
                b0[j] = vs[(s0 + 0) * PITCH + tx + 16 * j];
                b1[j] = vs[(s0 + 1) * PITCH + tx + 16 * j];
                b2[j] = vs[(s0 + 2) * PITCH + tx + 16 * j];
                b3[j] = vs[(s0 + 3) * PITCH + tx + 16 * j];
            }
            #pragma unroll
            for (int i = 0; i < 8; i++)
                #pragma unroll
                for (int j = 0; j < 4; j++) {
                    acc2[i][j] += a4[i].x * b0[j];
                    acc2[i][j] += a4[i].y * b1[j];
                    acc2[i][j] += a4[i].z * b2[j];
                    acc2[i][j] += a4[i].w * b3[j];
                }
        }

        // Scatter to output rows (output buffer pre-zeroed)
        #pragma unroll
        for (int i = 0; i < 8; i++) {
            int srow = sidx[ty + 16 * i];
            float* orow = out + (size_t)bh * S * D + (size_t)srow * D;
            #pragma unroll
            for (int j = 0; j < 4; j++) orow[tx + 16 * j] = acc2[i][j];
        }
    }
}

// ---------------------------------------------------------------------------
extern "C" void kernel_launch(void* const* d_in, const int* in_sizes, int n_in,
                              void* d_out, int out_size) {
    const float* q = (const float*)d_in[0];
    const float* k = (const float*)d_in[1];
    const float* v = (const float*)d_in[2];
    float* out = (float*)d_out;

    const int attn_smem = (3 * TOPK * PITCH + TOPK * TOPK) * (int)sizeof(float);
    cudaFuncSetAttribute(attn_kernel, cudaFuncAttributeMaxDynamicSharedMemorySize,
                         attn_smem);

    // Zero output (unselected positions must be 0)
    cudaMemsetAsync(d_out, 0, (size_t)out_size * sizeof(float), 0);

    // 1) importance: one warp per (b,h,s) row
    imp_kernel<<<(BH * S) / 8, 256>>>(q);

    // 2) top-128 per head
    topk_kernel<<<BH, 256>>>();

    // 3) gathered attention + scatter
    attn_kernel<<<BH, 256, attn_smem>>>(q, k, v, out);
}

// round 2
// speedup vs baseline: 1.3974x; 1.3974x over previous
#include <cuda_runtime.h>
#include <cstdint>

// Problem shape (fixed for this dataset entry)
#define B 8
#define H 12
#define S 4096
#define D 64
#define BH (B*H)        // 96
#define TOPK 128

// Scratch (device globals; no allocation allowed)
__device__ float g_imp[BH * S];     // importance scores
__device__ int   g_idx[BH * TOPK];  // selected indices per head

__device__ __forceinline__ unsigned key_of(float f) {
    unsigned u = __float_as_uint(f);
    return (u & 0x80000000u) ? ~u : (u | 0x80000000u);  // larger float -> larger uint
}

// ---------------------------------------------------------------------------
// Kernel 1: importance = mean + std(ddof=1) over D=64.
// 8 lanes per row (warp = 4 rows). Each lane: 2x LDG.128, 8 values.
// Reduction: 3 shfl (sum) + 3 shfl (var) per 4 rows.
// ---------------------------------------------------------------------------
__global__ __launch_bounds__(256)
void imp_kernel(const float* __restrict__ q) {
    int warp = (blockIdx.x * blockDim.x + threadIdx.x) >> 5;
    int lane = threadIdx.x & 31;
    int sub  = lane >> 3;          // row within the warp's group of 4
    int cl   = lane & 7;           // 8 lanes cover one row
    int row  = warp * 4 + sub;     // row < BH*S by grid sizing

    const float4* p = reinterpret_cast<const float4*>(q + (size_t)row * D) + cl;
    float4 a = p[0];               // cols [cl*4 .. cl*4+3]
    float4 b = p[8];               // cols [32+cl*4 .. 32+cl*4+3]

    float s = (a.x + a.y) + (a.z + a.w) + (b.x + b.y) + (b.z + b.w);
    #pragma unroll
    for (int o = 1; o < 8; o <<= 1) s += __shfl_xor_sync(0xFFFFFFFFu, s, o);
    float mean = s * (1.0f / 64.0f);

    float dx;
    float s2 = 0.0f;
    dx = a.x - mean; s2 += dx * dx;
    dx = a.y - mean; s2 += dx * dx;
    dx = a.z - mean; s2 += dx * dx;
    dx = a.w - mean; s2 += dx * dx;
    dx = b.x - mean; s2 += dx * dx;
    dx = b.y - mean; s2 += dx * dx;
    dx = b.z - mean; s2 += dx * dx;
    dx = b.w - mean; s2 += dx * dx;
    #pragma unroll
    for (int o = 1; o < 8; o <<= 1) s2 += __shfl_xor_sync(0xFFFFFFFFu, s2, o);

    if (cl == 0) g_imp[row] = mean + sqrtf(s2 * (1.0f / 63.0f));
}

// ---------------------------------------------------------------------------
// Kernel 2: exact top-128 per (b,h) via 4-pass MSB-first radix select.
// One block per head.
// ---------------------------------------------------------------------------
__global__ __launch_bounds__(256)
void topk_kernel() {
    __shared__ unsigned keys[S];   // 16 KB
    __shared__ int hist[256];
    __shared__ int s_digit, s_need, s_n;

    const int bh  = blockIdx.x;
    const int tid = threadIdx.x;
    const float* row = g_imp + (size_t)bh * S;

    for (int i = tid; i < S; i += 256) keys[i] = key_of(row[i]);

    unsigned prefix = 0u;
    int need = TOPK;

    #pragma unroll
    for (int shift = 24; shift >= 0; shift -= 8) {
        hist[tid] = 0;             // 256 threads, 256 bins
        __syncthreads();

        unsigned pmask = (shift == 24) ? 0u : (0xFFFFFFFFu << (shift + 8));
        for (int i = tid; i < S; i += 256) {
            unsigned u = keys[i];
            if ((u & pmask) == prefix)
                atomicAdd(&hist[(u >> shift) & 255u], 1);
        }
        __syncthreads();

        // warp 0: find highest digit d with count(digits > d) < need <= count(digits >= d)
        if (tid < 32) {
            int base = 255 - tid * 8;            // this lane covers [base-7 .. base], descending
            int h[8];
            int gs = 0;
            #pragma unroll
            for (int j = 0; j < 8; j++) { h[j] = hist[base - j]; gs += h[j]; }
            int pre = gs;                         // inclusive prefix over lanes (descending digits)
            #pragma unroll
            for (int o = 1; o < 32; o <<= 1) {
                int t = __shfl_up_sync(0xFFFFFFFFu, pre, o);
                if (tid >= o) pre += t;
            }
            int excl = pre - gs;                  // strictly-above-group count
            if (excl < need && need <= pre) {
                int cum = excl, j = 0;
                #pragma unroll
                for (; j < 8; j++) { cum += h[j]; if (cum >= need) break; }
                s_digit = base - j;
                s_need  = need - (cum - h[j]);
            }
        }
        __syncthreads();
        prefix |= ((unsigned)s_digit) << shift;
        need = s_need;
        __syncthreads();   // protect hist/s_digit reuse
    }

    const unsigned T = prefix;     // exact key of the 128th-largest element

    if (tid == 0) s_n = 0;
    __syncthreads();
    for (int i = tid; i < S; i += 256) {
        if (keys[i] > T) {
            int p = atomicAdd(&s_n, 1);
            g_idx[bh * TOPK + p] = i;
        }
    }
    __syncthreads();
    for (int i = tid; i < S; i += 256) {
        if (keys[i] == T) {
            int p = atomicAdd(&s_n, 1);
            if (p < TOPK) g_idx[bh * TOPK + p] = i;
        }
    }
}

// ---------------------------------------------------------------------------
// Kernel 3: gathered attention per head (unchanged from R1 — correct, ~roofline
// for SIMT fp32; revisit with tensor cores in a later round).
// ---------------------------------------------------------------------------
#define PITCH 68   // floats per smem row (128B data + pad)

__global__ __launch_bounds__(256, 1)
void attn_kernel(const float* __restrict__ q, const float* __restrict__ k,
                 const float* __restrict__ v, float* __restrict__ out) {
    extern __shared__ float sm[];
    float* qs = sm;                        // 128 x PITCH
    float* ks = qs + TOPK * PITCH;
    float* vs = ks + TOPK * PITCH;
    float* sc = vs + TOPK * PITCH;         // 128 x 128 scores
    __shared__ int sidx[TOPK];

    const int bh  = blockIdx.x;
    const int tid = threadIdx.x;
    if (tid < TOPK) sidx[tid] = g_idx[bh * TOPK + tid];
    __syncthreads();

    const size_t base = (size_t)bh * S * D;

    // Gather q_s,k_s,v_s: 2 threads per row, 8 float4 each
    {
        int r = tid >> 1, half = tid & 1;
        size_t goff = base + (size_t)sidx[r] * D + half * 32;
        const float4* gq = reinterpret_cast<const float4*>(q + goff);
        const float4* gk = reinterpret_cast<const float4*>(k + goff);
        const float4* gv = reinterpret_cast<const float4*>(v + goff);
        float* dq = qs + r * PITCH + half * 32;
        float* dk = ks + r * PITCH + half * 32;
        float* dv = vs + r * PITCH + half * 32;
        #pragma unroll
        for (int i = 0; i < 8; i++) {
            reinterpret_cast<float4*>(dq)[i] = gq[i];
            reinterpret_cast<float4*>(dk)[i] = gk[i];
            reinterpret_cast<float4*>(dv)[i] = gv[i];
        }
    }
    __syncthreads();

    const int tx = tid & 15, ty = tid >> 4;

    // GEMM1: scores = q_s k_s^T * 0.125; 8x8 tile per thread
    {
        float acc[8][8];
        #pragma unroll
        for (int i = 0; i < 8; i++)
            #pragma unroll
            for (int j = 0; j < 8; j++) acc[i][j] = 0.0f;

        #pragma unroll
        for (int d = 0; d < D; d += 4) {
            float4 a[8], b[8];
            #pragma unroll
            for (int i = 0; i < 8; i++)
                a[i] = *reinterpret_cast<const float4*>(qs + (ty + 16 * i) * PITCH + d);
            #pragma unroll
            for (int j = 0; j < 8; j++)
                b[j] = *reinterpret_cast<const float4*>(ks + (tx + 16 * j) * PITCH + d);
            #pragma unroll
            for (int i = 0; i < 8; i++)
                #pragma unroll
                for (int j = 0; j < 8; j++) {
                    acc[i][j] += a[i].x * b[j].x;
                    acc[i][j] += a[i].y * b[j].y;
                    acc[i][j] += a[i].z * b[j].z;
                    acc[i][j] += a[i].w * b[j].w;
                }
        }
        const float scale = 0.125f;
        #pragma unroll
        for (int i = 0; i < 8; i++)
            #pragma unroll
            for (int j = 0; j < 8; j++)
                sc[(ty + 16 * i) * TOPK + (tx + 16 * j)] = acc[i][j] * scale;
    }
    __syncthreads();

    // Row softmax (one warp per 16 rows)
    {
        int lane = tid & 31, wid = tid >> 5;
        for (int r = wid; r < TOPK; r += 8) {
            float* row = sc + r * TOPK;
            float x[4];
            float m = -1e30f;
            #pragma unroll
            for (int c = 0; c < 4; c++) { x[c] = row[lane + 32 * c]; m = fmaxf(m, x[c]); }
            #pragma unroll
            for (int o = 16; o; o >>= 1) m = fmaxf(m, __shfl_xor_sync(0xFFFFFFFFu, m, o));
            float ssum = 0.0f;
            #pragma unroll
            for (int c = 0; c < 4; c++) { x[c] = __expf(x[c] - m); ssum += x[c]; }
            #pragma unroll
            for (int o = 16; o; o >>= 1) ssum += __shfl_xor_sync(0xFFFFFFFFu, ssum, o);
            float inv = 1.0f / ssum;
            #pragma unroll
            for (int c = 0; c < 4; c++) row[lane + 32 * c] = x[c] * inv;
        }
    }
    __syncthreads();

    // GEMM2: out_s = attn @ v_s; 8x4 tile per thread; scatter rows
    {
        float acc2[8][4];
        #pragma unroll
        for (int i = 0; i < 8; i++)
            #pragma unroll
            for (int j = 0; j < 4; j++) acc2[i][j] = 0.0f;

        #pragma unroll 4
        for (int s0 = 0; s0 < TOPK; s0 += 4) {
            float4 a4[8];
            #pragma unroll
            for (int i = 0; i < 8; i++)
                a4[i] = *reinterpret_cast<const float4*>(sc + (ty + 16 * i) * TOPK + s0);
            float b0[4], b1[4], b2[4], b3[4];
            #pragma unroll
            for (int j = 0; j < 4; j++) {
                b0[j] = vs[(s0 + 0) * PITCH + tx + 16 * j];
                b1[j] = vs[(s0 + 1) * PITCH + tx + 16 * j];
                b2[j] = vs[(s0 + 2) * PITCH + tx + 16 * j];
                b3[j] = vs[(s0 + 3) * PITCH + tx + 16 * j];
            }
            #pragma unroll
            for (int i = 0; i < 8; i++)
                #pragma unroll
                for (int j = 0; j < 4; j++) {
                    acc2[i][j] += a4[i].x * b0[j];
                    acc2[i][j] += a4[i].y * b1[j];
                    acc2[i][j] += a4[i].z * b2[j];
                    acc2[i][j] += a4[i].w * b3[j];
                }
        }

        #pragma unroll
        for (int i = 0; i < 8; i++) {
            int srow = sidx[ty + 16 * i];
            float* orow = out + (size_t)bh * S * D + (size_t)srow * D;
            #pragma unroll
            for (int j = 0; j < 4; j++) orow[tx + 16 * j] = acc2[i][j];
        }
    }
}

// ---------------------------------------------------------------------------
extern "C" void kernel_launch(void* const* d_in, const int* in_sizes, int n_in,
                              void* d_out, int out_size) {
    const float* q = (const float*)d_in[0];
    const float* k = (const float*)d_in[1];
    const float* v = (const float*)d_in[2];
    float* out = (float*)d_out;

    // Lazily created side stream + events for forked graph capture.
    // (Host-side handles only; no device memory. Same work recorded on every
    //  call -> deterministic.)
    static cudaStream_t s1 = nullptr;
    static cudaEvent_t  e0 = nullptr, e2 = nullptr;
    if (s1 == nullptr) {
        cudaStreamCreateWithFlags(&s1, cudaStreamNonBlocking);
        cudaEventCreateWithFlags(&e0, cudaEventDisableTiming);
        cudaEventCreateWithFlags(&e2, cudaEventDisableTiming);
    }

    const int attn_smem = (3 * TOPK * PITCH + TOPK * TOPK) * (int)sizeof(float);
    cudaFuncSetAttribute(attn_kernel, cudaFuncAttributeMaxDynamicSharedMemorySize,
                         attn_smem);

    // Fork: zero the 100MB output on the side stream while imp/topk run.
    cudaEventRecord(e0, 0);
    cudaStreamWaitEvent(s1, e0, 0);
    cudaMemsetAsync(d_out, 0, (size_t)out_size * sizeof(float), s1);
    cudaEventRecord(e2, s1);

    // 1) importance: warp handles 4 rows
    imp_kernel<<<(BH * S) / 32, 256>>>(q);

    // 2) exact top-128 per head (radix select)
    topk_kernel<<<BH, 256>>>();

    // Join: attn writes into the zeroed output
    cudaStreamWaitEvent(0, e2, 0);

    // 3) gathered attention + scatter
    attn_kernel<<<BH, 256, attn_smem>>>(q, k, v, out);
}

// round 3
// speedup vs baseline: 1.4475x; 1.0359x over previous
#include <cuda_runtime.h>
#include <cstdint>

#define B 8
#define H 12
#define S 4096
#define D 64
#define BH (B*H)        // 96
#define TOPK 128
#define QROWS 64        // q-rows per attn CTA (2 CTAs per head)

// Scratch (device globals; no allocation allowed)
__device__ float    g_imp[BH * S];        // importance scores
__device__ int      g_idx[BH * TOPK];     // selected indices per head
__device__ unsigned g_selmask[BH * 128];  // 4096-bit selected-row bitmap per head

__device__ __forceinline__ unsigned key_of(float f) {
    unsigned u = __float_as_uint(f);
    return (u & 0x80000000u) ? ~u : (u | 0x80000000u);  // larger float -> larger uint
}

// ---------------------------------------------------------------------------
// Kernel 1: importance = mean + std(ddof=1) over D=64.
// 8 lanes per row; each warp covers 8 rows (2 per lane-group) -> 4 independent
// LDG.128 per thread for MLP.
// ---------------------------------------------------------------------------
__global__ __launch_bounds__(256)
void imp_kernel(const float* __restrict__ q) {
    int warp = (blockIdx.x * blockDim.x + threadIdx.x) >> 5;
    int lane = threadIdx.x & 31;
    int sub  = lane >> 3;          // 0..3
    int cl   = lane & 7;           // 8 lanes per row
    int r0   = warp * 8 + sub;     // first row
    int r1   = r0 + 4;             // second row

    const float4* p0 = reinterpret_cast<const float4*>(q + (size_t)r0 * D) + cl;
    const float4* p1 = reinterpret_cast<const float4*>(q + (size_t)r1 * D) + cl;
    float4 a0 = p0[0], b0 = p0[8];
    float4 a1 = p1[0], b1 = p1[8];

    float s0 = (a0.x + a0.y) + (a0.z + a0.w) + (b0.x + b0.y) + (b0.z + b0.w);
    float s1 = (a1.x + a1.y) + (a1.z + a1.w) + (b1.x + b1.y) + (b1.z + b1.w);
    #pragma unroll
    for (int o = 1; o < 8; o <<= 1) {
        s0 += __shfl_xor_sync(0xFFFFFFFFu, s0, o);
        s1 += __shfl_xor_sync(0xFFFFFFFFu, s1, o);
    }
    float m0 = s0 * (1.0f / 64.0f);
    float m1 = s1 * (1.0f / 64.0f);

    float dx, v0 = 0.0f, v1 = 0.0f;
    dx = a0.x - m0; v0 += dx * dx;  dx = a0.y - m0; v0 += dx * dx;
    dx = a0.z - m0; v0 += dx * dx;  dx = a0.w - m0; v0 += dx * dx;
    dx = b0.x - m0; v0 += dx * dx;  dx = b0.y - m0; v0 += dx * dx;
    dx = b0.z - m0; v0 += dx * dx;  dx = b0.w - m0; v0 += dx * dx;
    dx = a1.x - m1; v1 += dx * dx;  dx = a1.y - m1; v1 += dx * dx;
    dx = a1.z - m1; v1 += dx * dx;  dx = a1.w - m1; v1 += dx * dx;
    dx = b1.x - m1; v1 += dx * dx;  dx = b1.y - m1; v1 += dx * dx;
    dx = b1.z - m1; v1 += dx * dx;  dx = b1.w - m1; v1 += dx * dx;
    #pragma unroll
    for (int o = 1; o < 8; o <<= 1) {
        v0 += __shfl_xor_sync(0xFFFFFFFFu, v0, o);
        v1 += __shfl_xor_sync(0xFFFFFFFFu, v1, o);
    }

    if (cl == 0) {
        g_imp[r0] = m0 + sqrtf(v0 * (1.0f / 63.0f));
        g_imp[r1] = m1 + sqrtf(v1 * (1.0f / 63.0f));
    }
}

// ---------------------------------------------------------------------------
// Kernel 2: exact top-128 per head via 4-pass MSB radix select + bitmap.
// ---------------------------------------------------------------------------
__global__ __launch_bounds__(256)
void topk_kernel() {
    __shared__ unsigned keys[S];       // 16 KB
    __shared__ int hist[256];
    __shared__ unsigned mask[128];     // selected-row bitmap
    __shared__ int s_digit, s_need, s_n;

    const int bh  = blockIdx.x;
    const int tid = threadIdx.x;
    const float* row = g_imp + (size_t)bh * S;

    for (int i = tid; i < S; i += 256) keys[i] = key_of(row[i]);
    if (tid < 128) mask[tid] = 0u;

    unsigned prefix = 0u;
    int need = TOPK;

    #pragma unroll
    for (int shift = 24; shift >= 0; shift -= 8) {
        hist[tid] = 0;
        __syncthreads();

        unsigned pmask = (shift == 24) ? 0u : (0xFFFFFFFFu << (shift + 8));
        for (int i = tid; i < S; i += 256) {
            unsigned u = keys[i];
            if ((u & pmask) == prefix)
                atomicAdd(&hist[(u >> shift) & 255u], 1);
        }
        __syncthreads();

        if (tid < 32) {
            int base = 255 - tid * 8;
            int h[8];
            int gs = 0;
            #pragma unroll
            for (int j = 0; j < 8; j++) { h[j] = hist[base - j]; gs += h[j]; }
            int pre = gs;
            #pragma unroll
            for (int o = 1; o < 32; o <<= 1) {
                int t = __shfl_up_sync(0xFFFFFFFFu, pre, o);
                if (tid >= o) pre += t;
            }
            int excl = pre - gs;
            if (excl < need && need <= pre) {
                int cum = excl, j = 0;
                #pragma unroll
                for (; j < 8; j++) { cum += h[j]; if (cum >= need) break; }
                s_digit = base - j;
                s_need  = need - (cum - h[j]);
            }
        }
        __syncthreads();
        prefix |= ((unsigned)s_digit) << shift;
        need = s_need;
        __syncthreads();
    }

    const unsigned T = prefix;

    if (tid == 0) s_n = 0;
    __syncthreads();
    for (int i = tid; i < S; i += 256) {
        if (keys[i] > T) {
            int p = atomicAdd(&s_n, 1);
            g_idx[bh * TOPK + p] = i;
        }
    }
    __syncthreads();
    for (int i = tid; i < S; i += 256) {
        if (keys[i] == T) {
            int p = atomicAdd(&s_n, 1);
            if (p < TOPK) g_idx[bh * TOPK + p] = i;
        }
    }
    __syncthreads();
    // bitmap from the final selection (exactly consistent with g_idx)
    if (tid < TOPK) {
        int i = g_idx[bh * TOPK + tid];
        atomicOr(&mask[i >> 5], 1u << (i & 31));
    }
    __syncthreads();
    if (tid < 128) g_selmask[bh * 128 + tid] = mask[tid];
}

// ---------------------------------------------------------------------------
// Kernel 3: zero all UNSELECTED rows of the output (97% of the 100 MB).
// 4 blocks per head; runs concurrently with attn_kernel (disjoint rows).
// ---------------------------------------------------------------------------
__global__ __launch_bounds__(256)
void zero_kernel(float* __restrict__ out) {
    __shared__ unsigned mask[32];
    const int bh   = blockIdx.x >> 2;
    const int quad = blockIdx.x & 3;
    const int tid  = threadIdx.x;
    if (tid < 32) mask[tid] = g_selmask[bh * 128 + quad * 32 + tid];
    __syncthreads();

    const int rowbase = quad * 1024;
    float4* obase = reinterpret_cast<float4*>(out + (size_t)bh * S * D) + rowbase * 16;
    const float4 z = make_float4(0.f, 0.f, 0.f, 0.f);

    // 1024 rows x 16 float4; lanes 0-15 cover one row (256B coalesced)
    for (int i = tid; i < 1024 * 16; i += 256) {
        int r = i >> 4;
        if (!(mask[r >> 5] & (1u << (r & 31))))
            obase[i] = z;
    }
}

// ---------------------------------------------------------------------------
// Kernel 4: gathered attention. 2 CTAs per head; each computes 64 q-rows
// against all 128 k/v rows and scatters its 64 output rows.
// ---------------------------------------------------------------------------
#define PITCH 68   // floats per smem row (128B data + pad)

__global__ __launch_bounds__(256, 1)
void attn_kernel(const float* __restrict__ q, const float* __restrict__ k,
                 const float* __restrict__ v, float* __restrict__ out) {
    extern __shared__ float sm[];
    float* qs = sm;                          // QROWS x PITCH
    float* ks = qs + QROWS * PITCH;          // TOPK x PITCH
    float* vs = ks + TOPK * PITCH;           // TOPK x PITCH
    float* sc = vs + TOPK * PITCH;           // QROWS x TOPK
    __shared__ int sidx[TOPK];

    const int bh   = blockIdx.x >> 1;
    const int half = blockIdx.x & 1;         // which 64 q-slots this CTA owns
    const int tid  = threadIdx.x;
    if (tid < TOPK) sidx[tid] = g_idx[bh * TOPK + tid];
    __syncthreads();

    const size_t base = (size_t)bh * S * D;

    // Gather k,v: all 128 rows; 2 threads per row
    {
        int r = tid >> 1, hh = tid & 1;
        size_t goff = base + (size_t)sidx[r] * D + hh * 32;
        const float4* gk = reinterpret_cast<const float4*>(k + goff);
        const float4* gv = reinterpret_cast<const float4*>(v + goff);
        float* dk = ks + r * PITCH + hh * 32;
        float* dv = vs + r * PITCH + hh * 32;
        #pragma unroll
        for (int i = 0; i < 8; i++) {
            reinterpret_cast<float4*>(dk)[i] = gk[i];
            reinterpret_cast<float4*>(dv)[i] = gv[i];
        }
    }
    // Gather q: this CTA's 64 rows; 4 threads per row
    {
        int r = tid >> 2, qq = tid & 3;
        size_t goff = base + (size_t)sidx[half * QROWS + r] * D + qq * 16;
        const float4* gq = reinterpret_cast<const float4*>(q + goff);
        float* dq = qs + r * PITCH + qq * 16;
        #pragma unroll
        for (int i = 0; i < 4; i++)
            reinterpret_cast<float4*>(dq)[i] = gq[i];
    }
    __syncthreads();

    const int tx = tid & 15, ty = tid >> 4;   // tx: 16 col groups, ty: 16 row groups

    // GEMM1: sc[64x128] = qs @ ks^T * 0.125; 4x8 tile per thread
    {
        float acc[4][8];
        #pragma unroll
        for (int i = 0; i < 4; i++)
            #pragma unroll
            for (int j = 0; j < 8; j++) acc[i][j] = 0.0f;

        #pragma unroll
        for (int d = 0; d < D; d += 4) {
            float4 a[4], b[8];
            #pragma unroll
            for (int i = 0; i < 4; i++)
                a[i] = *reinterpret_cast<const float4*>(qs + (ty + 16 * i) * PITCH + d);
            #pragma unroll
            for (int j = 0; j < 8; j++)
                b[j] = *reinterpret_cast<const float4*>(ks + (tx + 16 * j) * PITCH + d);
            #pragma unroll
            for (int i = 0; i < 4; i++)
                #pragma unroll
                for (int j = 0; j < 8; j++) {
                    acc[i][j] += a[i].x * b[j].x;
                    acc[i][j] += a[i].y * b[j].y;
                    acc[i][j] += a[i].z * b[j].z;
                    acc[i][j] += a[i].w * b[j].w;
                }
        }
        const float scale = 0.125f;
        #pragma unroll
        for (int i = 0; i < 4; i++)
            #pragma unroll
            for (int j = 0; j < 8; j++)
                sc[(ty + 16 * i) * TOPK + (tx + 16 * j)] = acc[i][j] * scale;
    }
    __syncthreads();

    // Row softmax: 8 warps, 8 rows each
    {
        int lane = tid & 31, wid = tid >> 5;
        #pragma unroll
        for (int rr = 0; rr < QROWS / 8; rr++) {
            int r = wid + 8 * rr;
            float* row = sc + r * TOPK;
            float x[4];
            float m = -1e30f;
            #pragma unroll
            for (int c = 0; c < 4; c++) { x[c] = row[lane + 32 * c]; m = fmaxf(m, x[c]); }
            #pragma unroll
            for (int o = 16; o; o >>= 1) m = fmaxf(m, __shfl_xor_sync(0xFFFFFFFFu, m, o));
            float ssum = 0.0f;
            #pragma unroll
            for (int c = 0; c < 4; c++) { x[c] = __expf(x[c] - m); ssum += x[c]; }
            #pragma unroll
            for (int o = 16; o; o >>= 1) ssum += __shfl_xor_sync(0xFFFFFFFFu, ssum, o);
            float inv = 1.0f / ssum;
            #pragma unroll
            for (int c = 0; c < 4; c++) row[lane + 32 * c] = x[c] * inv;
        }
    }
    __syncthreads();

    // GEMM2: out[64x64] = attn @ vs; 4x4 tile per thread; scatter rows
    {
        float acc2[4][4];
        #pragma unroll
        for (int i = 0; i < 4; i++)
            #pragma unroll
            for (int j = 0; j < 4; j++) acc2[i][j] = 0.0f;

        #pragma unroll 4
        for (int s0 = 0; s0 < TOPK; s0 += 4) {
            float4 a4[4];
            #pragma unroll
            for (int i = 0; i < 4; i++)
                a4[i] = *reinterpret_cast<const float4*>(sc + (ty + 16 * i) * TOPK + s0);
            float b0[4], b1[4], b2[4], b3[4];
            #pragma unroll
            for (int j = 0; j < 4; j++) {
                b0[j] = vs[(s0 + 0) * PITCH + tx + 16 * j];
                b1[j] = vs[(s0 + 1) * PITCH + tx + 16 * j];
                b2[j] = vs[(s0 + 2) * PITCH + tx + 16 * j];
                b3[j] = vs[(s0 + 3) * PITCH + tx + 16 * j];
            }
            #pragma unroll
            for (int i = 0; i < 4; i++)
                #pragma unroll
                for (int j = 0; j < 4; j++) {
                    acc2[i][j] += a4[i].x * b0[j];
                    acc2[i][j] += a4[i].y * b1[j];
                    acc2[i][j] += a4[i].z * b2[j];
                    acc2[i][j] += a4[i].w * b3[j];
                }
        }

        #pragma unroll
        for (int i = 0; i < 4; i++) {
            int srow = sidx[half * QROWS + ty + 16 * i];
            float* orow = out + (size_t)bh * S * D + (size_t)srow * D;
            #pragma unroll
            for (int j = 0; j < 4; j++) orow[tx + 16 * j] = acc2[i][j];
        }
    }
}

// ---------------------------------------------------------------------------
extern "C" void kernel_launch(void* const* d_in, const int* in_sizes, int n_in,
                              void* d_out, int out_size) {
    const float* q = (const float*)d_in[0];
    const float* k = (const float*)d_in[1];
    const float* v = (const float*)d_in[2];
    float* out = (float*)d_out;

    static cudaStream_t s1 = nullptr;
    static cudaEvent_t  e0 = nullptr, e1 = nullptr;
    if (s1 == nullptr) {
        cudaStreamCreateWithFlags(&s1, cudaStreamNonBlocking);
        cudaEventCreateWithFlags(&e0, cudaEventDisableTiming);
        cudaEventCreateWithFlags(&e1, cudaEventDisableTiming);
    }

    const int attn_smem = ((QROWS + 2 * TOPK) * PITCH + QROWS * TOPK) * (int)sizeof(float);
    cudaFuncSetAttribute(attn_kernel, cudaFuncAttributeMaxDynamicSharedMemorySize,
                         attn_smem);

    // 1) importance: warp handles 8 rows
    imp_kernel<<<(BH * S) / 64, 256>>>(q);

    // 2) exact top-128 per head + selected bitmap
    topk_kernel<<<BH, 256>>>();

    // Fork after topk: zero unselected rows on side stream while attn computes
    // selected rows on the main stream (disjoint output rows).
    cudaEventRecord(e0, 0);
    cudaStreamWaitEvent(s1, e0, 0);
    zero_kernel<<<BH * 4, 256, 0, s1>>>(out);
    cudaEventRecord(e1, s1);

    // 3) gathered attention + scatter (2 CTAs per head)
    attn_kernel<<<BH * 2, 256, attn_smem>>>(q, k, v, out);

    // Join
    cudaStreamWaitEvent(0, e1, 0);
}

// round 4
// speedup vs baseline: 1.4808x; 1.0230x over previous
#include <cuda_runtime.h>
#include <cstdint>

#define B 8
#define H 12
#define S 4096
#define D 64
#define BH (B*H)        // 96
#define TOPK 128
#define QROWS 64        // q-rows per attn CTA (2 CTAs per head)

// Scratch (device globals; no allocation allowed)
__device__ float    g_imp[BH * S];        // importance scores
__device__ int      g_idx[BH * TOPK];     // selected indices per head
__device__ unsigned g_selmask[BH * 128];  // 4096-bit selected-row bitmap per head

__device__ __forceinline__ unsigned key_of(float f) {
    unsigned u = __float_as_uint(f);
    return (u & 0x80000000u) ? ~u : (u | 0x80000000u);  // larger float -> larger uint
}

// ---------------------------------------------------------------------------
// Kernel 1: importance = mean + std(ddof=1) over D=64.
// 8 lanes per row; each lane-group handles 4 rows -> 8 independent LDG.128
// per thread (MLP=8), 512B coalesced per row-group.
// ---------------------------------------------------------------------------
__global__ __launch_bounds__(256)
void imp_kernel(const float* __restrict__ q) {
    int warp = (blockIdx.x * blockDim.x + threadIdx.x) >> 5;
    int lane = threadIdx.x & 31;
    int sub  = lane >> 3;          // 0..3
    int cl   = lane & 7;           // 8 lanes per row
    int r0   = warp * 16 + sub;    // rows r0, r0+4, r0+8, r0+12

    float4 a[4], b[4];
    #pragma unroll
    for (int t = 0; t < 4; t++) {
        const float4* p = reinterpret_cast<const float4*>(q + (size_t)(r0 + 4 * t) * D) + cl;
        a[t] = p[0];
        b[t] = p[8];
    }

    float s[4];
    #pragma unroll
    for (int t = 0; t < 4; t++)
        s[t] = (a[t].x + a[t].y) + (a[t].z + a[t].w) +
               (b[t].x + b[t].y) + (b[t].z + b[t].w);
    #pragma unroll
    for (int o = 1; o < 8; o <<= 1)
        #pragma unroll
        for (int t = 0; t < 4; t++)
            s[t] += __shfl_xor_sync(0xFFFFFFFFu, s[t], o);

    float m[4], var[4];
    #pragma unroll
    for (int t = 0; t < 4; t++) {
        m[t] = s[t] * (1.0f / 64.0f);
        float dx, acc = 0.0f;
        dx = a[t].x - m[t]; acc += dx * dx;  dx = a[t].y - m[t]; acc += dx * dx;
        dx = a[t].z - m[t]; acc += dx * dx;  dx = a[t].w - m[t]; acc += dx * dx;
        dx = b[t].x - m[t]; acc += dx * dx;  dx = b[t].y - m[t]; acc += dx * dx;
        dx = b[t].z - m[t]; acc += dx * dx;  dx = b[t].w - m[t]; acc += dx * dx;
        var[t] = acc;
    }
    #pragma unroll
    for (int o = 1; o < 8; o <<= 1)
        #pragma unroll
        for (int t = 0; t < 4; t++)
            var[t] += __shfl_xor_sync(0xFFFFFFFFu, var[t], o);

    if (cl == 0) {
        #pragma unroll
        for (int t = 0; t < 4; t++)
            g_imp[r0 + 4 * t] = m[t] + sqrtf(var[t] * (1.0f / 63.0f));
    }
}

// ---------------------------------------------------------------------------
// Kernel 2: exact top-128 per head via 4-pass MSB radix select + bitmap.
// ---------------------------------------------------------------------------
__global__ __launch_bounds__(256)
void topk_kernel() {
    __shared__ unsigned keys[S];       // 16 KB
    __shared__ int hist[256];
    __shared__ unsigned mask[128];
    __shared__ int s_digit, s_need, s_n;

    const int bh  = blockIdx.x;
    const int tid = threadIdx.x;
    const float* row = g_imp + (size_t)bh * S;

    for (int i = tid; i < S; i += 256) keys[i] = key_of(row[i]);
    if (tid < 128) mask[tid] = 0u;

    unsigned prefix = 0u;
    int need = TOPK;

    #pragma unroll
    for (int shift = 24; shift >= 0; shift -= 8) {
        hist[tid] = 0;
        __syncthreads();

        unsigned pmask = (shift == 24) ? 0u : (0xFFFFFFFFu << (shift + 8));
        for (int i = tid; i < S; i += 256) {
            unsigned u = keys[i];
            if ((u & pmask) == prefix)
                atomicAdd(&hist[(u >> shift) & 255u], 1);
        }
        __syncthreads();

        if (tid < 32) {
            int base = 255 - tid * 8;
            int h[8];
            int gs = 0;
            #pragma unroll
            for (int j = 0; j < 8; j++) { h[j] = hist[base - j]; gs += h[j]; }
            int pre = gs;
            #pragma unroll
            for (int o = 1; o < 32; o <<= 1) {
                int t = __shfl_up_sync(0xFFFFFFFFu, pre, o);
                if (tid >= o) pre += t;
            }
            int excl = pre - gs;
            if (excl < need && need <= pre) {
                int cum = excl, j = 0;
                #pragma unroll
                for (; j < 8; j++) { cum += h[j]; if (cum >= need) break; }
                s_digit = base - j;
                s_need  = need - (cum - h[j]);
            }
        }
        __syncthreads();
        prefix |= ((unsigned)s_digit) << shift;
        need = s_need;
        __syncthreads();
    }

    const unsigned T = prefix;

    if (tid == 0) s_n = 0;
    __syncthreads();
    for (int i = tid; i < S; i += 256) {
        if (keys[i] > T) {
            int p = atomicAdd(&s_n, 1);
            g_idx[bh * TOPK + p] = i;
        }
    }
    __syncthreads();
    for (int i = tid; i < S; i += 256) {
        if (keys[i] == T) {
            int p = atomicAdd(&s_n, 1);
            if (p < TOPK) g_idx[bh * TOPK + p] = i;
        }
    }
    __syncthreads();
    if (tid < TOPK) {
        int i = g_idx[bh * TOPK + tid];
        atomicOr(&mask[i >> 5], 1u << (i & 31));
    }
    __syncthreads();
    if (tid < 128) g_selmask[bh * 128 + tid] = mask[tid];
}

// ---------------------------------------------------------------------------
// Kernel 3: zero all UNSELECTED output rows; overlaps attn (disjoint rows).
// ---------------------------------------------------------------------------
__global__ __launch_bounds__(256)
void zero_kernel(float* __restrict__ out) {
    __shared__ unsigned mask[32];
    const int bh   = blockIdx.x >> 2;
    const int quad = blockIdx.x & 3;
    const int tid  = threadIdx.x;
    if (tid < 32) mask[tid] = g_selmask[bh * 128 + quad * 32 + tid];
    __syncthreads();

    float4* obase = reinterpret_cast<float4*>(out + (size_t)bh * S * D) + (quad * 1024) * 16;
    const float4 z = make_float4(0.f, 0.f, 0.f, 0.f);

    for (int i = tid; i < 1024 * 16; i += 256) {
        int r = i >> 4;
        if (!(mask[r >> 5] & (1u << (r & 31))))
            obase[i] = z;
    }
}

// ---------------------------------------------------------------------------
// Kernel 4: gathered attention. 2 CTAs/head, 64 q-rows each.
// Scores live in registers; softmax via 16-lane shuffles; probs staged into
// the dead ks region for GEMM2. smem 87KB -> 2 CTAs/SM.
// ---------------------------------------------------------------------------
#define PITCH  68    // k/v/q smem row pitch (floats)
#define PPITCH 132   // prob-matrix pitch (floats), multiple of 4

__global__ __launch_bounds__(256, 2)
void attn_kernel(const float* __restrict__ q, const float* __restrict__ k,
                 const float* __restrict__ v, float* __restrict__ out) {
    extern __shared__ float sm[];
    float* qs = sm;                          // QROWS x PITCH   (17.4 KB)
    float* ks = qs + QROWS * PITCH;          // TOPK x PITCH    (34.8 KB), reused for probs
    float* vs = ks + TOPK * PITCH;           // TOPK x PITCH    (34.8 KB)
    float* ps = ks;                          // QROWS x PPITCH  (33.8 KB) alias
    __shared__ int sidx[TOPK];

    const int bh   = blockIdx.x >> 1;
    const int half = blockIdx.x & 1;
    const int tid  = threadIdx.x;
    if (tid < TOPK) sidx[tid] = g_idx[bh * TOPK + tid];
    __syncthreads();

    const size_t base = (size_t)bh * S * D;

    // Gather k,v (128 rows; 2 threads/row) and q (64 rows; 4 threads/row)
    {
        int r = tid >> 1, hh = tid & 1;
        size_t goff = base + (size_t)sidx[r] * D + hh * 32;
        const float4* gk = reinterpret_cast<const float4*>(k + goff);
        const float4* gv = reinterpret_cast<const float4*>(v + goff);
        float* dk = ks + r * PITCH + hh * 32;
        float* dv = vs + r * PITCH + hh * 32;
        #pragma unroll
        for (int i = 0; i < 8; i++) {
            reinterpret_cast<float4*>(dk)[i] = gk[i];
            reinterpret_cast<float4*>(dv)[i] = gv[i];
        }
    }
    {
        int r = tid >> 2, qq = tid & 3;
        size_t goff = base + (size_t)sidx[half * QROWS + r] * D + qq * 16;
        const float4* gq = reinterpret_cast<const float4*>(q + goff);
        float* dq = qs + r * PITCH + qq * 16;
        #pragma unroll
        for (int i = 0; i < 4; i++)
            reinterpret_cast<float4*>(dq)[i] = gq[i];
    }
    __syncthreads();

    const int tx = tid & 15, ty = tid >> 4;

    // GEMM1 (to registers): acc[i][j] = dot(q[ty+16i], k[tx+16j]) * 0.125
    float acc[4][8];
    #pragma unroll
    for (int i = 0; i < 4; i++)
        #pragma unroll
        for (int j = 0; j < 8; j++) acc[i][j] = 0.0f;

    #pragma unroll
    for (int d = 0; d < D; d += 4) {
        float4 a[4], b[8];
        #pragma unroll
        for (int i = 0; i < 4; i++)
            a[i] = *reinterpret_cast<const float4*>(qs + (ty + 16 * i) * PITCH + d);
        #pragma unroll
        for (int j = 0; j < 8; j++)
            b[j] = *reinterpret_cast<const float4*>(ks + (tx + 16 * j) * PITCH + d);
        #pragma unroll
        for (int i = 0; i < 4; i++)
            #pragma unroll
            for (int j = 0; j < 8; j++) {
                acc[i][j] += a[i].x * b[j].x;
                acc[i][j] += a[i].y * b[j].y;
                acc[i][j] += a[i].z * b[j].z;
                acc[i][j] += a[i].w * b[j].w;
            }
    }

    // Register softmax. Row (ty+16i) is held by the 16 lanes sharing ty
    // (lanes (ty&1)*16 + tx within the warp): reduce over xor 1,2,4,8.
    #pragma unroll
    for (int i = 0; i < 4; i++) {
        float mx = acc[i][0];
        #pragma unroll
        for (int j = 1; j < 8; j++) mx = fmaxf(mx, acc[i][j]);
        #pragma unroll
        for (int o = 1; o < 16; o <<= 1)
            mx = fmaxf(mx, __shfl_xor_sync(0xFFFFFFFFu, mx, o));
        mx *= 0.125f;
        float ssum = 0.0f;
        #pragma unroll
        for (int j = 0; j < 8; j++) {
            acc[i][j] = __expf(acc[i][j] * 0.125f - mx);
            ssum += acc[i][j];
        }
        #pragma unroll
        for (int o = 1; o < 16; o <<= 1)
            ssum += __shfl_xor_sync(0xFFFFFFFFu, ssum, o);
        float inv = 1.0f / ssum;
        #pragma unroll
        for (int j = 0; j < 8; j++) acc[i][j] *= inv;
    }

    __syncthreads();   // everyone done reading ks
    #pragma unroll
    for (int i = 0; i < 4; i++)
        #pragma unroll
        for (int j = 0; j < 8; j++)
            ps[(ty + 16 * i) * PPITCH + (tx + 16 * j)] = acc[i][j];
    __syncthreads();

    // GEMM2: out[64x64] = probs @ vs; 4x4 tile per thread; scatter rows
    {
        float acc2[4][4];
        #pragma unroll
        for (int i = 0; i < 4; i++)
            #pragma unroll
            for (int j = 0; j < 4; j++) acc2[i][j] = 0.0f;

        #pragma unroll 4
        for (int s0 = 0; s0 < TOPK; s0 += 4) {
            float4 a4[4];
            #pragma unroll
            for (int i = 0; i < 4; i++)
                a4[i] = *reinterpret_cast<const float4*>(ps + (ty + 16 * i) * PPITCH + s0);
            float b0[4], b1[4], b2[4], b3[4];
            #pragma unroll
            for (int j = 0; j < 4; j++) {
                b0[j] = vs[(s0 + 0) * PITCH + tx + 16 * j];
                b1[j] = vs[(s0 + 1) * PITCH + tx + 16 * j];
                b2[j] = vs[(s0 + 2) * PITCH + tx + 16 * j];
                b3[j] = vs[(s0 + 3) * PITCH + tx + 16 * j];
            }
            #pragma unroll
            for (int i = 0; i < 4; i++)
                #pragma unroll
                for (int j = 0; j < 4; j++) {
                    acc2[i][j] += a4[i].x * b0[j];
                    acc2[i][j] += a4[i].y * b1[j];
                    acc2[i][j] += a4[i].z * b2[j];
                    acc2[i][j] += a4[i].w * b3[j];
                }
        }

        #pragma unroll
        for (int i = 0; i < 4; i++) {
            int srow = sidx[half * QROWS + ty + 16 * i];
            float* orow = out + (size_t)bh * S * D + (size_t)srow * D;
            #pragma unroll
            for (int j = 0; j < 4; j++) orow[tx + 16 * j] = acc2[i][j];
        }
    }
}

// ---------------------------------------------------------------------------
extern "C" void kernel_launch(void* const* d_in, const int* in_sizes, int n_in,
                              void* d_out, int out_size) {
    const float* q = (const float*)d_in[0];
    const float* k = (const float*)d_in[1];
    const float* v = (const float*)d_in[2];
    float* out = (float*)d_out;

    static cudaStream_t s1 = nullptr;
    static cudaEvent_t  e0 = nullptr, e1 = nullptr;
    if (s1 == nullptr) {
        cudaStreamCreateWithFlags(&s1, cudaStreamNonBlocking);
        cudaEventCreateWithFlags(&e0, cudaEventDisableTiming);
        cudaEventCreateWithFlags(&e1, cudaEventDisableTiming);
    }

    const int attn_smem = (QROWS * PITCH + 2 * TOPK * PITCH) * (int)sizeof(float);
    cudaFuncSetAttribute(attn_kernel, cudaFuncAttributeMaxDynamicSharedMemorySize,
                         attn_smem);

    // 1) importance: warp handles 16 rows
    imp_kernel<<<(BH * S) / 128, 256>>>(q);

    // 2) exact top-128 per head + selected bitmap
    topk_kernel<<<BH, 256>>>();

    // Fork: zero unselected rows on side stream while attn computes selected.
    cudaEventRecord(e0, 0);
    cudaStreamWaitEvent(s1, e0, 0);
    zero_kernel<<<BH * 4, 256, 0, s1>>>(out);
    cudaEventRecord(e1, s1);

    // 3) gathered attention + scatter (2 CTAs per head, 2 CTAs/SM)
    attn_kernel<<<BH * 2, 256, attn_smem>>>(q, k, v, out);

    // Join
    cudaStreamWaitEvent(0, e1, 0);
}